// round 5
// baseline (speedup 1.0000x reference)
#include <cuda_runtime.h>
#include <cstdint>

// out = self_tensor; out[sorted_index[i], :] += value[i, :]
// N=262144 rows, M=1048576 updates, D=128 cols, fp32. sorted_index SORTED,
// delivered as int32 by the harness.
//
// Pass 1: CSR row-start offsets (starts[r] = lower_bound(idx, r)).
// Pass 2: one warp per output row streams its run of value rows (float4,
//   MLP=4) on top of the self row, single store. Traffic = minimal 776MB.
// PDL: pass-1 triggers launch completion at entry; pass-2 issues its
//   self-row load before cudaGridDependencySynchronize(), overlapping
//   pass-1 execution + launch latency under pass-2's leading DRAM reads.

static constexpr int D4 = 32;          // 128 floats = 32 float4/row
static constexpr int MAX_ROWS = 262144;

__device__ int g_starts[MAX_ROWS + 1];

__global__ void build_starts_kernel(const int* __restrict__ idx,
                                    int m, int n_rows) {
#if __CUDA_ARCH__ >= 900
    cudaTriggerProgrammaticLaunchCompletion();
#endif
    int i = blockIdx.x * blockDim.x + threadIdx.x;
    if (i > m) return;
    int b = (i < m) ? __ldg(&idx[i]) : n_rows;        // virtual idx[m] = n
    int a = (i > 0) ? __ldg(&idx[i - 1]) : -1;
    for (int r = a + 1; r <= b; ++r) g_starts[r] = i;
}

__global__ void scatter_add_rows_kernel(const float* __restrict__ self_t,
                                        const float* __restrict__ value,
                                        float* __restrict__ out,
                                        int n_rows) {
    const int warp = (blockIdx.x * blockDim.x + threadIdx.x) >> 5;
    const int lane = threadIdx.x & 31;
    if (warp >= n_rows) return;

    const int r = warp;

    const float4* __restrict__ selfv = reinterpret_cast<const float4*>(self_t);
    const float4* __restrict__ valv  = reinterpret_cast<const float4*>(value);
    float4* __restrict__ outv        = reinterpret_cast<float4*>(out);

    // self row does not depend on pass-1: issue before the grid sync
    float4 acc = __ldcs(&selfv[(size_t)r * D4 + lane]);

#if __CUDA_ARCH__ >= 900
    cudaGridDependencySynchronize();
#endif

    int s = 0;
    if (lane < 2) s = g_starts[r + lane];
    const int start = __shfl_sync(0xffffffffu, s, 0);
    const int end   = __shfl_sync(0xffffffffu, s, 1);

    const float4* p = valv + (size_t)start * D4 + lane;
    int n = end - start;

    while (n >= 4) {
        float4 v0 = __ldcs(p);
        float4 v1 = __ldcs(p + D4);
        float4 v2 = __ldcs(p + 2 * D4);
        float4 v3 = __ldcs(p + 3 * D4);
        acc.x += v0.x; acc.y += v0.y; acc.z += v0.z; acc.w += v0.w;
        acc.x += v1.x; acc.y += v1.y; acc.z += v1.z; acc.w += v1.w;
        acc.x += v2.x; acc.y += v2.y; acc.z += v2.z; acc.w += v2.w;
        acc.x += v3.x; acc.y += v3.y; acc.z += v3.z; acc.w += v3.w;
        p += 4 * D4;
        n -= 4;
    }
    if (n >= 2) {
        float4 v0 = __ldcs(p);
        float4 v1 = __ldcs(p + D4);
        acc.x += v0.x; acc.y += v0.y; acc.z += v0.z; acc.w += v0.w;
        acc.x += v1.x; acc.y += v1.y; acc.z += v1.z; acc.w += v1.w;
        p += 2 * D4;
        n -= 2;
    }
    if (n) {
        float4 v = __ldcs(p);
        acc.x += v.x; acc.y += v.y; acc.z += v.z; acc.w += v.w;
    }

    __stcs(&outv[(size_t)r * D4 + lane], acc);
}

extern "C" void kernel_launch(void* const* d_in, const int* in_sizes, int n_in,
                              void* d_out, int out_size) {
    const float* self_t = (const float*)d_in[0];  // (N, 128) fp32
    const float* value  = (const float*)d_in[1];  // (M, 128) fp32
    const int*   idx    = (const int*)d_in[2];    // (M,) sorted
    // d_in[3] = pos, unused

    const int m      = in_sizes[2];       // 1048576
    const int n_rows = out_size / 128;    // 262144 (<= MAX_ROWS)

    {
        const int threads = 512;
        const int blocks = (m + 1 + threads - 1) / threads;
        build_starts_kernel<<<blocks, threads>>>(idx, m, n_rows);
    }
    {
        const int threads = 256;          // 8 warps/block
        const int blocks = (n_rows * 32 + threads - 1) / threads;

        cudaLaunchConfig_t cfg = {};
        cfg.gridDim  = dim3(blocks, 1, 1);
        cfg.blockDim = dim3(threads, 1, 1);
        cfg.dynamicSmemBytes = 0;
        cfg.stream = 0;

        cudaLaunchAttribute attr[1];
        attr[0].id = cudaLaunchAttributeProgrammaticStreamSerialization;
        attr[0].val.programmaticStreamSerializationAllowed = 1;
        cfg.attrs = attr;
        cfg.numAttrs = 1;

        float* outp = (float*)d_out;
        cudaError_t err = cudaLaunchKernelEx(&cfg, scatter_add_rows_kernel,
                                             self_t, value, outp, n_rows);
        if (err != cudaSuccess) {
            // fallback: plain serialized launch
            scatter_add_rows_kernel<<<blocks, threads>>>(self_t, value,
                                                         outp, n_rows);
        }
    }
}